// round 13
// baseline (speedup 1.0000x reference)
#include <cuda_runtime.h>
#include <cuda_bf16.h>
#include <math.h>
#include <stdint.h>

#define NBATCH 4
#define NPTS   4096
#define KNB    32
#define NPIXT  (NBATCH*NPTS*KNB)   /* 524288 pixels */

/* winograd conv smem: V[16j][16ci][129] + U[16j][16ci][64co] floats */
#define SV_FLOATS (16*16*129)          /* 33024 */
#define SU_FLOATS (16*16*64)           /* 16384 */
#define WCONV_SMEM ((SV_FLOATS + SU_FLOATS)*4)   /* 197632 B */

/* ----------------------------- device scratch ----------------------------- */
__device__ float d_f[NBATCH*NPTS*8];
__device__ int   d_idx[NPIXT];
__device__ float d_g [(size_t)NPIXT*64];   /* raw graph feats (pre-GN) */
__device__ float d_h1[(size_t)NPIXT*64];   /* conv1 activated output   */
__device__ float d_stats[32];              /* [b][grp][sum,sumsq]      */
__device__ float d_U[2*16*64*64];          /* winograd weights [conv][j][ci][co] */

struct Params {
    float gnsc[4][64];
    float gnsh[4][64];
    float bn1sc[64], bn1sh[64];
    float bn2sc[64], bn2sh[64];
    float wc[3][64];               /* folded w_img @ w_blk */
    float bc[3];                   /* folded bias          */
};
__device__ Params d_par;

/* ------------------------- K0: input MLP f = opc@W+b ----------------------- */
__global__ void k_f(const float* __restrict__ opc, const float* __restrict__ w_in,
                    const float* __restrict__ b_in) {
    int t = blockIdx.x * 256 + threadIdx.x;            /* 0..16383 */
    if (blockIdx.x == 0 && threadIdx.x < 32) d_stats[threadIdx.x] = 0.f;
    const float* p = opc + (size_t)t * 3;
    float x = p[0], y = p[1], z = p[2];
#pragma unroll
    for (int d = 0; d < 8; d++) {
        float a = __ldg(b_in + d);
        a = fmaf(x, __ldg(w_in + d*3 + 0), a);
        a = fmaf(y, __ldg(w_in + d*3 + 1), a);
        a = fmaf(z, __ldg(w_in + d*3 + 2), a);
        d_f[(size_t)t*8 + d] = a;
    }
}

/* ------------------------------ K1: exact KNN ------------------------------ */
__global__ void __launch_bounds__(256) k_knn(const float* __restrict__ opc) {
    extern __shared__ float sm[];
    float* px  = sm;
    float* py  = sm + 4096;
    float* pz  = sm + 8192;
    float* psq = sm + 12288;
    int tid = threadIdx.x;
    int b = blockIdx.x >> 9;
    const float* base = opc + (size_t)b * NPTS * 3;
    for (int i = tid; i < NPTS; i += 256) {
        float x = base[i*3], y = base[i*3+1], z = base[i*3+2];
        px[i] = x; py[i] = y; pz[i] = z;
        psq[i] = __fadd_rn(__fadd_rn(__fmul_rn(x,x), __fmul_rn(y,y)), __fmul_rn(z,z));
    }
    __syncthreads();

    int warp = tid >> 5, lane = tid & 31;
    int nq = (blockIdx.x & 511) * 8 + warp;
    float qx = px[nq], qy = py[nq], qz = pz[nq], qs = psq[nq];

    unsigned long long arr[32];
#pragma unroll
    for (int j = 0; j < 32; j++) arr[j] = ~0ull;
    unsigned long long mx = ~0ull;

    for (int m = lane; m < NPTS; m += 32) {
        float dot  = __fadd_rn(__fadd_rn(__fmul_rn(qx, px[m]), __fmul_rn(qy, py[m])),
                               __fmul_rn(qz, pz[m]));
        float dist = __fsub_rn(__fadd_rn(qs, psq[m]), __fmul_rn(2.0f, dot));
        unsigned u = __float_as_uint(dist);
        u = (u & 0x80000000u) ? ~u : (u | 0x80000000u);
        unsigned long long key = ((unsigned long long)u << 32) | (unsigned)m;
        if (key < mx) {
            arr[31] = key;
#pragma unroll
            for (int j = 31; j > 0; --j) {
                unsigned long long a0 = arr[j-1], a1 = arr[j];
                unsigned long long lo = a0 < a1 ? a0 : a1;
                unsigned long long hi = a0 < a1 ? a1 : a0;
                arr[j-1] = lo; arr[j] = hi;
            }
            mx = arr[31];
        }
    }

    unsigned long long cur = arr[0];
    int* op = d_idx + ((size_t)(b * NPTS + nq)) * 32;
    for (int kk = 0; kk < 32; ++kk) {
        unsigned long long mval = cur;
#pragma unroll
        for (int off = 16; off; off >>= 1) {
            unsigned long long o = __shfl_xor_sync(0xffffffffu, mval, off);
            if (o < mval) mval = o;
        }
        unsigned msk = __ballot_sync(0xffffffffu, cur == mval);
        int src = __ffs(msk) - 1;
        if (lane == src) {
#pragma unroll
            for (int j = 0; j < 31; j++) arr[j] = arr[j+1];
            arr[31] = ~0ull;
            cur = arr[0];
        }
        if (lane == 0) op[kk] = (int)(mval & 0xffffffffu);
    }
}

/* ----------------- K2: edge features + 16->64 GEMM + GN stats -------------- */
__global__ void __launch_bounds__(256) k_edge(const float* __restrict__ wg) {
    __shared__ float swg[1024];
    __shared__ float ssum[8];
    int tid = threadIdx.x;
    for (int u = tid; u < 1024; u += 256) swg[u] = wg[u];
    if (tid < 8) ssum[tid] = 0.f;
    __syncthreads();

    int p = blockIdx.x * 256 + tid;
    int b = p >> 17;
    int n = (p >> 5) & 4095;
    int id = d_idx[p];
    const float4* fq4 = (const float4*)(d_f + (size_t)(b*NPTS + n ) * 8);
    const float4* nb4 = (const float4*)(d_f + (size_t)(b*NPTS + id) * 8);
    float4 fa = fq4[0], fb = fq4[1], na = nb4[0], nb = nb4[1];

    float feat[16];
    feat[0] = na.x - fa.x; feat[1] = na.y - fa.y; feat[2] = na.z - fa.z; feat[3] = na.w - fa.w;
    feat[4] = nb.x - fb.x; feat[5] = nb.y - fb.y; feat[6] = nb.z - fb.z; feat[7] = nb.w - fb.w;
    feat[8]  = fa.x; feat[9]  = fa.y; feat[10] = fa.z; feat[11] = fa.w;
    feat[12] = fb.x; feat[13] = fb.y; feat[14] = fb.z; feat[15] = fb.w;

    float* gout = d_g + (size_t)p * 64;
    float ps[4], pss[4];
#pragma unroll
    for (int g = 0; g < 4; g++) { ps[g] = 0.f; pss[g] = 0.f; }

#pragma unroll
    for (int d0 = 0; d0 < 64; d0 += 4) {
        float4 o;
        float* opp = (float*)&o;
#pragma unroll
        for (int s = 0; s < 4; s++) {
            int d = d0 + s;
            const float4* wr = (const float4*)(swg + d * 16);
            float a = 0.f;
#pragma unroll
            for (int t = 0; t < 4; t++) {
                float4 wv = wr[t];
                a = fmaf(feat[4*t+0], wv.x, a);
                a = fmaf(feat[4*t+1], wv.y, a);
                a = fmaf(feat[4*t+2], wv.z, a);
                a = fmaf(feat[4*t+3], wv.w, a);
            }
            opp[s] = a;
            ps[d0 >> 4] += a;
            pss[d0 >> 4] = fmaf(a, a, pss[d0 >> 4]);
        }
        *(float4*)(gout + d0) = o;
    }

#pragma unroll
    for (int g = 0; g < 4; g++) {
#pragma unroll
        for (int off = 16; off; off >>= 1) {
            ps[g]  += __shfl_xor_sync(0xffffffffu, ps[g],  off);
            pss[g] += __shfl_xor_sync(0xffffffffu, pss[g], off);
        }
    }
    if ((tid & 31) == 0) {
#pragma unroll
        for (int g = 0; g < 4; g++) {
            atomicAdd(&ssum[2*g],   ps[g]);
            atomicAdd(&ssum[2*g+1], pss[g]);
        }
    }
    __syncthreads();
    if (tid < 8) atomicAdd(&d_stats[b*8 + tid], ssum[tid]);
}

/* -------------------- K3: finalize all derived parameters ------------------ */
__global__ void k_final(const float* __restrict__ gn_g, const float* __restrict__ gn_b,
                        const float* __restrict__ bn1_g, const float* __restrict__ bn1_b,
                        const float* __restrict__ bn1_m, const float* __restrict__ bn1_v,
                        const float* __restrict__ bn2_g, const float* __restrict__ bn2_b,
                        const float* __restrict__ bn2_m, const float* __restrict__ bn2_v,
                        const float* __restrict__ w_blk, const float* __restrict__ b_blk,
                        const float* __restrict__ w_img, const float* __restrict__ b_img) {
    __shared__ float smu[16], srs[16];
    int tid = threadIdx.x;
    const float inv = 1.0f / 2097152.0f;   /* N*K*16 */
    if (tid < 16) {
        float s  = d_stats[ (tid>>2)*8 + (tid&3)*2 ];
        float ss = d_stats[ (tid>>2)*8 + (tid&3)*2 + 1 ];
        float mu = s * inv;
        float var = ss * inv - mu * mu;
        smu[tid] = mu;
        srs[tid] = rsqrtf(var + 1e-5f);
    }
    __syncthreads();
    {   /* GN affine per (b,d): 256 entries */
        int b = tid >> 6, d = tid & 63, grp = d >> 4;
        float rs = srs[b*4 + grp], mu = smu[b*4 + grp];
        float sc = gn_g[d] * rs;
        d_par.gnsc[b][d] = sc;
        d_par.gnsh[b][d] = gn_b[d] - mu * sc;
    }
    if (tid < 64) {
        int d = tid;
        float s1 = bn1_g[d] * rsqrtf(bn1_v[d] + 1e-5f);
        d_par.bn1sc[d] = s1; d_par.bn1sh[d] = bn1_b[d] - bn1_m[d] * s1;
        float s2 = bn2_g[d] * rsqrtf(bn2_v[d] + 1e-5f);
        d_par.bn2sc[d] = s2; d_par.bn2sh[d] = bn2_b[d] - bn2_m[d] * s2;
    }
    if (tid < 192) {
        int i = tid >> 6, c = tid & 63;
        float a = 0.f;
        for (int d = 0; d < 64; d++) a = fmaf(w_img[i*64 + d], w_blk[d*64 + c], a);
        d_par.wc[i][c] = a;
    }
    if (tid < 3) {
        float a = b_img[tid];
        for (int d = 0; d < 64; d++) a = fmaf(w_img[tid*64 + d], b_blk[d], a);
        d_par.bc[tid] = a;
    }
}

/* --------------- K_uprep: winograd weight transform U = G g G^T ------------ */
__global__ void k_uprep(const float* __restrict__ w1, const float* __restrict__ w2) {
    int t = blockIdx.x * 256 + threadIdx.x;       /* 0..8191 */
    if (t >= 8192) return;
    int conv = t >> 12;
    int r = t & 4095;
    int ci = r >> 6, co = r & 63;
    const float* w = conv ? w2 : w1;
    float g[3][3];
#pragma unroll
    for (int ky = 0; ky < 3; ky++)
#pragma unroll
        for (int kx = 0; kx < 3; kx++)
            g[ky][kx] = w[(((size_t)ky*3 + kx)*64 + ci)*64 + co];
    float t4[4][3];
#pragma unroll
    for (int kx = 0; kx < 3; kx++) {
        t4[0][kx] = g[0][kx];
        t4[1][kx] = 0.5f*(g[0][kx] + g[1][kx] + g[2][kx]);
        t4[2][kx] = 0.5f*(g[0][kx] - g[1][kx] + g[2][kx]);
        t4[3][kx] = g[2][kx];
    }
#pragma unroll
    for (int jy = 0; jy < 4; jy++) {
        float a = t4[jy][0], bq = t4[jy][1], c = t4[jy][2];
        float u0 = a;
        float u1 = 0.5f*(a + bq + c);
        float u2 = 0.5f*(a - bq + c);
        float u3 = c;
        d_U[(((size_t)conv*16 + jy*4 + 0)*64 + ci)*64 + co] = u0;
        d_U[(((size_t)conv*16 + jy*4 + 1)*64 + ci)*64 + co] = u1;
        d_U[(((size_t)conv*16 + jy*4 + 2)*64 + ci)*64 + co] = u2;
        d_U[(((size_t)conv*16 + jy*4 + 3)*64 + ci)*64 + co] = u3;
    }
}

/* ---------------- K4/K5: winograd F(2x2,3x3) conv, C=64 -------------------- */
/* block: 16 n-rows x 32 w = 128 tiles(2x2); 1024 threads = tile(128) x co-octet(8).
   MODE 1: in = GN(leaky(d_g)) -> out h1 = relu(bn1(conv))
   MODE 2: in = d_h1 -> relu(bn2(conv)+g_act) -> head -> max_k -> out        */
template<int MODE>
__global__ void __launch_bounds__(1024, 1) k_wconv(const float* __restrict__ pc,
                                                   float* __restrict__ out) {
    extern __shared__ float smd[];
    float* s_V = smd;                  /* [j16][ci16][129] */
    float* s_U = smd + SV_FLOATS;      /* [j16][ci16][co64] */
    __shared__ float s_gnsc[64], s_gnsh[64], s_bsc[64], s_bsh[64], s_wc[195];

    int tid = threadIdx.x;
    int b  = blockIdx.x >> 8;
    int n0 = (blockIdx.x & 255) << 4;
    int tile = tid & 127;              /* 0..127 */
    int og   = tid >> 7;               /* 0..7 co octet */
    int tn = tile >> 4, tw = tile & 15;

    if (tid < 64) {
        s_gnsc[tid] = d_par.gnsc[b][tid];
        s_gnsh[tid] = d_par.gnsh[b][tid];
        if (MODE == 1) { s_bsc[tid] = d_par.bn1sc[tid]; s_bsh[tid] = d_par.bn1sh[tid]; }
        else           { s_bsc[tid] = d_par.bn2sc[tid]; s_bsh[tid] = d_par.bn2sh[tid]; }
    }
    if (MODE == 2 && tid < 195) s_wc[tid] = ((const float*)d_par.wc)[tid];

    const float* gin = (MODE == 1 ? d_g : d_h1) + (size_t)b * NPTS * 32 * 64;

    float racc[32];                    /* 4 pixels x 8 co */
#pragma unroll
    for (int q = 0; q < 32; q++) racc[q] = 0.f;

    for (int cc = 0; cc < 64; cc += 16) {
        /* load U chunk [16j][16ci][64co] */
        {
            const float* ub = d_U + (size_t)(MODE - 1) * 65536;
            for (int u = tid; u < SU_FLOATS; u += 1024) {
                int j  = u >> 10;
                int ci = (u >> 6) & 15;
                int co = u & 63;
                s_U[u] = ub[((size_t)j*64 + cc + ci)*64 + co];
            }
        }
        /* Phase A: input transform V = B^T d B (2048 tasks over 1024 thr) */
#pragma unroll
        for (int it = 0; it < 2; it++) {
            int uu = it * 1024 + tid;
            int tl = uu >> 4, ci = uu & 15;
            int ttn = tl >> 4, ttw = tl & 15;
            int nb = n0 + ttn*2 - 1, wb = ttw*2 - 1;
            int c = cc + ci;
            float gsc = s_gnsc[c], gsh = s_gnsh[c];
            float d[4][4];
#pragma unroll
            for (int y = 0; y < 4; y++) {
                int n = nb + y;
                bool nok = ((unsigned)n < 4096u);
#pragma unroll
                for (int x = 0; x < 4; x++) {
                    int w = wb + x;
                    float v = 0.f;
                    if (nok && (unsigned)w < 32u) {
                        v = gin[((size_t)(n*32 + w))*64 + c];
                        if (MODE == 1) {
                            float tt = fmaf(v, gsc, gsh);
                            v = tt >= 0.f ? tt : 0.2f*tt;
                        }
                    }
                    d[y][x] = v;
                }
            }
            float tA[4][4];
#pragma unroll
            for (int x = 0; x < 4; x++) {
                tA[0][x] = d[0][x] - d[2][x];
                tA[1][x] = d[1][x] + d[2][x];
                tA[2][x] = d[2][x] - d[1][x];
                tA[3][x] = d[1][x] - d[3][x];
            }
#pragma unroll
            for (int jy = 0; jy < 4; jy++) {
                float V0 = tA[jy][0] - tA[jy][2];
                float V1 = tA[jy][1] + tA[jy][2];
                float V2 = tA[jy][2] - tA[jy][1];
                float V3 = tA[jy][1] - tA[jy][3];
                s_V[((jy*4 + 0)*16 + ci)*129 + tl] = V0;
                s_V[((jy*4 + 1)*16 + ci)*129 + tl] = V1;
                s_V[((jy*4 + 2)*16 + ci)*129 + tl] = V2;
                s_V[((jy*4 + 3)*16 + ci)*129 + tl] = V3;
            }
        }
        __syncthreads();

        /* Phase B: per-j GEMM (8co x 16ci) + inverse-transform scatter */
#pragma unroll 1
        for (int j = 0; j < 16; j++) {
            float m[8];
#pragma unroll
            for (int k = 0; k < 8; k++) m[k] = 0.f;
            const float* vp = s_V + (j*16)*129 + tile;
            const float* up = s_U + (j*16)*64 + og*8;
#pragma unroll
            for (int ci = 0; ci < 16; ci++) {
                float v = vp[ci*129];
                const float4* ur = (const float4*)(up + ci*64);
                float4 u0 = ur[0], u1 = ur[1];
                m[0] = fmaf(v, u0.x, m[0]); m[1] = fmaf(v, u0.y, m[1]);
                m[2] = fmaf(v, u0.z, m[2]); m[3] = fmaf(v, u0.w, m[3]);
                m[4] = fmaf(v, u1.x, m[4]); m[5] = fmaf(v, u1.y, m[5]);
                m[6] = fmaf(v, u1.z, m[6]); m[7] = fmaf(v, u1.w, m[7]);
            }
            int jy = j >> 2, jx = j & 3;
            float cy[2], cx[2];
            cy[0] = (jy == 3) ? 0.f : 1.f;
            cy[1] = (jy == 0) ? 0.f : ((jy == 1) ? 1.f : -1.f);
            cx[0] = (jx == 3) ? 0.f : 1.f;
            cx[1] = (jx == 0) ? 0.f : ((jx == 1) ? 1.f : -1.f);
#pragma unroll
            for (int py = 0; py < 2; py++) {
#pragma unroll
                for (int px = 0; px < 2; px++) {
                    float cf = cy[py] * cx[px];
                    if (cf != 0.f) {
                        float* o = racc + (py*2 + px)*8;
#pragma unroll
                        for (int k = 0; k < 8; k++) o[k] = fmaf(cf, m[k], o[k]);
                    }
                }
            }
        }
        __syncthreads();
    }

    /* ------------------------------ epilogue ------------------------------- */
    if (MODE == 1) {
#pragma unroll
        for (int py = 0; py < 2; py++) {
#pragma unroll
            for (int px = 0; px < 2; px++) {
                int n = n0 + tn*2 + py, w = tw*2 + px;
                size_t pix = ((size_t)(b*NPTS + n))*32 + w;
                float* op = d_h1 + pix*64 + og*8;
                const float* a = racc + (py*2 + px)*8;
#pragma unroll
                for (int q = 0; q < 2; q++) {
                    int c = og*8 + q*4;
                    float4 v;
                    v.x = fmaxf(fmaf(a[q*4+0], s_bsc[c+0], s_bsh[c+0]), 0.f);
                    v.y = fmaxf(fmaf(a[q*4+1], s_bsc[c+1], s_bsh[c+1]), 0.f);
                    v.z = fmaxf(fmaf(a[q*4+2], s_bsc[c+2], s_bsh[c+2]), 0.f);
                    v.w = fmaxf(fmaf(a[q*4+3], s_bsc[c+3], s_bsh[c+3]), 0.f);
                    *(float4*)(op + q*4) = v;
                }
            }
        }
    } else {
        float* yp = s_V;   /* alias: [16n][32w][8og][3] = 12288 floats */
#pragma unroll
        for (int py = 0; py < 2; py++) {
#pragma unroll
            for (int px = 0; px < 2; px++) {
                int nl = tn*2 + py, w = tw*2 + px;
                size_t pix = ((size_t)(b*NPTS + n0 + nl))*32 + w;
                const float* a = racc + (py*2 + px)*8;
                float4 g4[2];
                g4[0] = ((const float4*)(d_g + pix*64 + og*8))[0];
                g4[1] = ((const float4*)(d_g + pix*64 + og*8))[1];
                const float* gf = (const float*)g4;
                float y0 = 0.f, y1 = 0.f, y2 = 0.f;
#pragma unroll
                for (int k = 0; k < 8; k++) {
                    int c = og*8 + k;
                    float gv = fmaf(gf[k], s_gnsc[c], s_gnsh[c]);
                    gv = gv >= 0.f ? gv : 0.2f*gv;
                    float h = fmaxf(fmaf(a[k], s_bsc[c], s_bsh[c]) + gv, 0.f);
                    y0 = fmaf(h, s_wc[c], y0);
                    y1 = fmaf(h, s_wc[64+c], y1);
                    y2 = fmaf(h, s_wc[128+c], y2);
                }
                int idx = ((nl*32 + w)*8 + og)*3;
                yp[idx] = y0; yp[idx+1] = y1; yp[idx+2] = y2;
            }
        }
        __syncthreads();
        if (tid < 512) {
            int nl = tid >> 5, w = tid & 31;
            float y0 = s_wc[192], y1 = s_wc[193], y2 = s_wc[194];
#pragma unroll
            for (int q = 0; q < 8; q++) {
                int idx = ((nl*32 + w)*8 + q)*3;
                y0 += yp[idx]; y1 += yp[idx+1]; y2 += yp[idx+2];
            }
#pragma unroll
            for (int off = 16; off; off >>= 1) {
                y0 = fmaxf(y0, __shfl_xor_sync(0xffffffffu, y0, off));
                y1 = fmaxf(y1, __shfl_xor_sync(0xffffffffu, y1, off));
                y2 = fmaxf(y2, __shfl_xor_sync(0xffffffffu, y2, off));
            }
            if (w == 0) {
                int n = n0 + nl;
                const float* pp = pc + ((size_t)(b*NPTS + n)) * 3;
                float* o = out + ((size_t)(b*NPTS + n)) * 6;
                o[0] = pp[0]; o[1] = pp[1]; o[2] = pp[2];
                float c0 = 1.f / (1.f + expf(-y0));
                float c1 = 1.f / (1.f + expf(-y1));
                float c2 = 1.f / (1.f + expf(-y2));
                o[3] = (c0 - 0.485f) / 0.229f;
                o[4] = (c1 - 0.456f) / 0.224f;
                o[5] = (c2 - 0.406f) / 0.225f;
            }
        }
    }
}

/* --------------------------------- launcher -------------------------------- */
extern "C" void kernel_launch(void* const* d_in, const int* in_sizes, int n_in,
                              void* d_out, int out_size) {
    const float* opc   = (const float*)d_in[0];
    const float* pc    = (const float*)d_in[1];
    const float* w_in  = (const float*)d_in[2];
    const float* b_in  = (const float*)d_in[3];
    const float* w_g   = (const float*)d_in[4];
    const float* gn_g  = (const float*)d_in[5];
    const float* gn_b  = (const float*)d_in[6];
    const float* w_c1  = (const float*)d_in[7];
    const float* bn1_g = (const float*)d_in[8];
    const float* bn1_b = (const float*)d_in[9];
    const float* bn1_m = (const float*)d_in[10];
    const float* bn1_v = (const float*)d_in[11];
    const float* w_c2  = (const float*)d_in[12];
    const float* bn2_g = (const float*)d_in[13];
    const float* bn2_b = (const float*)d_in[14];
    const float* bn2_m = (const float*)d_in[15];
    const float* bn2_v = (const float*)d_in[16];
    const float* w_blk = (const float*)d_in[17];
    const float* b_blk = (const float*)d_in[18];
    const float* w_img = (const float*)d_in[19];
    const float* b_img = (const float*)d_in[20];
    float* out = (float*)d_out;

    cudaFuncSetAttribute(k_knn, cudaFuncAttributeMaxDynamicSharedMemorySize, 65536);
    cudaFuncSetAttribute(k_wconv<1>, cudaFuncAttributeMaxDynamicSharedMemorySize, WCONV_SMEM);
    cudaFuncSetAttribute(k_wconv<2>, cudaFuncAttributeMaxDynamicSharedMemorySize, WCONV_SMEM);

    k_f    <<<64,   256>>>(opc, w_in, b_in);
    k_knn  <<<2048, 256, 65536>>>(opc);
    k_edge <<<2048, 256>>>(w_g);
    k_final<<<1,    256>>>(gn_g, gn_b, bn1_g, bn1_b, bn1_m, bn1_v,
                           bn2_g, bn2_b, bn2_m, bn2_v, w_blk, b_blk, w_img, b_img);
    k_uprep<<<32,   256>>>(w_c1, w_c2);
    k_wconv<1><<<1024, 1024, WCONV_SMEM>>>(pc, out);
    k_wconv<2><<<1024, 1024, WCONV_SMEM>>>(pc, out);
}

// round 15
// speedup vs baseline: 1.0827x; 1.0827x over previous
#include <cuda_runtime.h>
#include <cuda_bf16.h>
#include <math.h>
#include <stdint.h>

#define NBATCH 4
#define NPTS   4096
#define KNB    32
#define NPIXT  (NBATCH*NPTS*KNB)   /* 524288 pixels */

/* winograd conv smem: V[16j][16ci][66] + U[8j][16ci][64co] floats */
#define TSTR   66
#define SV_FLOATS (16*16*TSTR)         /* 16896 */
#define SU_FLOATS (8*16*64)            /* 8192  */
#define WCONV_SMEM ((SV_FLOATS + SU_FLOATS)*4)   /* 100352 B -> 2 blocks/SM */

/* ----------------------------- device scratch ----------------------------- */
__device__ float d_f[NBATCH*NPTS*8];
__device__ int   d_idx[NPIXT];
__device__ float d_g [(size_t)NPIXT*64];   /* raw graph feats (pre-GN) */
__device__ float d_h1[(size_t)NPIXT*64];   /* conv1 activated output   */
__device__ float d_stats[32];              /* [b][grp][sum,sumsq]      */
__device__ float d_U[2*16*64*64];          /* winograd weights [conv][j][ci][co] */

struct Params {
    float gnsc[4][64];
    float gnsh[4][64];
    float bn1sc[64], bn1sh[64];
    float bn2sc[64], bn2sh[64];
    float wc[3][64];               /* folded w_img @ w_blk */
    float bc[3];                   /* folded bias          */
};
__device__ Params d_par;

/* ------------------------- K0: input MLP f = opc@W+b ----------------------- */
__global__ void k_f(const float* __restrict__ opc, const float* __restrict__ w_in,
                    const float* __restrict__ b_in) {
    int t = blockIdx.x * 256 + threadIdx.x;            /* 0..16383 */
    if (blockIdx.x == 0 && threadIdx.x < 32) d_stats[threadIdx.x] = 0.f;
    const float* p = opc + (size_t)t * 3;
    float x = p[0], y = p[1], z = p[2];
#pragma unroll
    for (int d = 0; d < 8; d++) {
        float a = __ldg(b_in + d);
        a = fmaf(x, __ldg(w_in + d*3 + 0), a);
        a = fmaf(y, __ldg(w_in + d*3 + 1), a);
        a = fmaf(z, __ldg(w_in + d*3 + 2), a);
        d_f[(size_t)t*8 + d] = a;
    }
}

/* ------------------------------ K1: exact KNN ------------------------------ */
__global__ void __launch_bounds__(256) k_knn(const float* __restrict__ opc) {
    extern __shared__ float sm[];
    float* px  = sm;
    float* py  = sm + 4096;
    float* pz  = sm + 8192;
    float* psq = sm + 12288;
    int tid = threadIdx.x;
    int b = blockIdx.x >> 9;
    const float* base = opc + (size_t)b * NPTS * 3;
    for (int i = tid; i < NPTS; i += 256) {
        float x = base[i*3], y = base[i*3+1], z = base[i*3+2];
        px[i] = x; py[i] = y; pz[i] = z;
        psq[i] = __fadd_rn(__fadd_rn(__fmul_rn(x,x), __fmul_rn(y,y)), __fmul_rn(z,z));
    }
    __syncthreads();

    int warp = tid >> 5, lane = tid & 31;
    int nq = (blockIdx.x & 511) * 8 + warp;
    float qx = px[nq], qy = py[nq], qz = pz[nq], qs = psq[nq];

    unsigned long long arr[32];
#pragma unroll
    for (int j = 0; j < 32; j++) arr[j] = ~0ull;
    unsigned long long mx = ~0ull;

    for (int m = lane; m < NPTS; m += 32) {
        float dot  = __fadd_rn(__fadd_rn(__fmul_rn(qx, px[m]), __fmul_rn(qy, py[m])),
                               __fmul_rn(qz, pz[m]));
        float dist = __fsub_rn(__fadd_rn(qs, psq[m]), __fmul_rn(2.0f, dot));
        unsigned u = __float_as_uint(dist);
        u = (u & 0x80000000u) ? ~u : (u | 0x80000000u);
        unsigned long long key = ((unsigned long long)u << 32) | (unsigned)m;
        if (key < mx) {
            arr[31] = key;
#pragma unroll
            for (int j = 31; j > 0; --j) {
                unsigned long long a0 = arr[j-1], a1 = arr[j];
                unsigned long long lo = a0 < a1 ? a0 : a1;
                unsigned long long hi = a0 < a1 ? a1 : a0;
                arr[j-1] = lo; arr[j] = hi;
            }
            mx = arr[31];
        }
    }

    unsigned long long cur = arr[0];
    int* op = d_idx + ((size_t)(b * NPTS + nq)) * 32;
    for (int kk = 0; kk < 32; ++kk) {
        unsigned long long mval = cur;
#pragma unroll
        for (int off = 16; off; off >>= 1) {
            unsigned long long o = __shfl_xor_sync(0xffffffffu, mval, off);
            if (o < mval) mval = o;
        }
        unsigned msk = __ballot_sync(0xffffffffu, cur == mval);
        int src = __ffs(msk) - 1;
        if (lane == src) {
#pragma unroll
            for (int j = 0; j < 31; j++) arr[j] = arr[j+1];
            arr[31] = ~0ull;
            cur = arr[0];
        }
        if (lane == 0) op[kk] = (int)(mval & 0xffffffffu);
    }
}

/* ----------------- K2: edge features + 16->64 GEMM + GN stats -------------- */
__global__ void __launch_bounds__(256) k_edge(const float* __restrict__ wg) {
    __shared__ float swg[1024];
    __shared__ float ssum[8];
    int tid = threadIdx.x;
    for (int u = tid; u < 1024; u += 256) swg[u] = wg[u];
    if (tid < 8) ssum[tid] = 0.f;
    __syncthreads();

    int p = blockIdx.x * 256 + tid;
    int b = p >> 17;
    int n = (p >> 5) & 4095;
    int id = d_idx[p];
    const float4* fq4 = (const float4*)(d_f + (size_t)(b*NPTS + n ) * 8);
    const float4* nb4 = (const float4*)(d_f + (size_t)(b*NPTS + id) * 8);
    float4 fa = fq4[0], fb = fq4[1], na = nb4[0], nb = nb4[1];

    float feat[16];
    feat[0] = na.x - fa.x; feat[1] = na.y - fa.y; feat[2] = na.z - fa.z; feat[3] = na.w - fa.w;
    feat[4] = nb.x - fb.x; feat[5] = nb.y - fb.y; feat[6] = nb.z - fb.z; feat[7] = nb.w - fb.w;
    feat[8]  = fa.x; feat[9]  = fa.y; feat[10] = fa.z; feat[11] = fa.w;
    feat[12] = fb.x; feat[13] = fb.y; feat[14] = fb.z; feat[15] = fb.w;

    float* gout = d_g + (size_t)p * 64;
    float ps[4], pss[4];
#pragma unroll
    for (int g = 0; g < 4; g++) { ps[g] = 0.f; pss[g] = 0.f; }

#pragma unroll
    for (int d0 = 0; d0 < 64; d0 += 4) {
        float4 o;
        float* opp = (float*)&o;
#pragma unroll
        for (int s = 0; s < 4; s++) {
            int d = d0 + s;
            const float4* wr = (const float4*)(swg + d * 16);
            float a = 0.f;
#pragma unroll
            for (int t = 0; t < 4; t++) {
                float4 wv = wr[t];
                a = fmaf(feat[4*t+0], wv.x, a);
                a = fmaf(feat[4*t+1], wv.y, a);
                a = fmaf(feat[4*t+2], wv.z, a);
                a = fmaf(feat[4*t+3], wv.w, a);
            }
            opp[s] = a;
            ps[d0 >> 4] += a;
            pss[d0 >> 4] = fmaf(a, a, pss[d0 >> 4]);
        }
        *(float4*)(gout + d0) = o;
    }

#pragma unroll
    for (int g = 0; g < 4; g++) {
#pragma unroll
        for (int off = 16; off; off >>= 1) {
            ps[g]  += __shfl_xor_sync(0xffffffffu, ps[g],  off);
            pss[g] += __shfl_xor_sync(0xffffffffu, pss[g], off);
        }
    }
    if ((tid & 31) == 0) {
#pragma unroll
        for (int g = 0; g < 4; g++) {
            atomicAdd(&ssum[2*g],   ps[g]);
            atomicAdd(&ssum[2*g+1], pss[g]);
        }
    }
    __syncthreads();
    if (tid < 8) atomicAdd(&d_stats[b*8 + tid], ssum[tid]);
}

/* -------------------- K3: finalize all derived parameters ------------------ */
__global__ void k_final(const float* __restrict__ gn_g, const float* __restrict__ gn_b,
                        const float* __restrict__ bn1_g, const float* __restrict__ bn1_b,
                        const float* __restrict__ bn1_m, const float* __restrict__ bn1_v,
                        const float* __restrict__ bn2_g, const float* __restrict__ bn2_b,
                        const float* __restrict__ bn2_m, const float* __restrict__ bn2_v,
                        const float* __restrict__ w_blk, const float* __restrict__ b_blk,
                        const float* __restrict__ w_img, const float* __restrict__ b_img) {
    __shared__ float smu[16], srs[16];
    int tid = threadIdx.x;
    const float inv = 1.0f / 2097152.0f;   /* N*K*16 */
    if (tid < 16) {
        float s  = d_stats[ (tid>>2)*8 + (tid&3)*2 ];
        float ss = d_stats[ (tid>>2)*8 + (tid&3)*2 + 1 ];
        float mu = s * inv;
        float var = ss * inv - mu * mu;
        smu[tid] = mu;
        srs[tid] = rsqrtf(var + 1e-5f);
    }
    __syncthreads();
    {   /* GN affine per (b,d): 256 entries */
        int b = tid >> 6, d = tid & 63, grp = d >> 4;
        float rs = srs[b*4 + grp], mu = smu[b*4 + grp];
        float sc = gn_g[d] * rs;
        d_par.gnsc[b][d] = sc;
        d_par.gnsh[b][d] = gn_b[d] - mu * sc;
    }
    if (tid < 64) {
        int d = tid;
        float s1 = bn1_g[d] * rsqrtf(bn1_v[d] + 1e-5f);
        d_par.bn1sc[d] = s1; d_par.bn1sh[d] = bn1_b[d] - bn1_m[d] * s1;
        float s2 = bn2_g[d] * rsqrtf(bn2_v[d] + 1e-5f);
        d_par.bn2sc[d] = s2; d_par.bn2sh[d] = bn2_b[d] - bn2_m[d] * s2;
    }
    if (tid < 192) {
        int i = tid >> 6, c = tid & 63;
        float a = 0.f;
        for (int d = 0; d < 64; d++) a = fmaf(w_img[i*64 + d], w_blk[d*64 + c], a);
        d_par.wc[i][c] = a;
    }
    if (tid < 3) {
        float a = b_img[tid];
        for (int d = 0; d < 64; d++) a = fmaf(w_img[tid*64 + d], b_blk[d], a);
        d_par.bc[tid] = a;
    }
}

/* --------------- K_uprep: winograd weight transform U = G g G^T ------------ */
__global__ void k_uprep(const float* __restrict__ w1, const float* __restrict__ w2) {
    int t = blockIdx.x * 256 + threadIdx.x;       /* 0..8191 */
    if (t >= 8192) return;
    int conv = t >> 12;
    int r = t & 4095;
    int ci = r >> 6, co = r & 63;
    const float* w = conv ? w2 : w1;
    float g[3][3];
#pragma unroll
    for (int ky = 0; ky < 3; ky++)
#pragma unroll
        for (int kx = 0; kx < 3; kx++)
            g[ky][kx] = w[(((size_t)ky*3 + kx)*64 + ci)*64 + co];
    float t4[4][3];
#pragma unroll
    for (int kx = 0; kx < 3; kx++) {
        t4[0][kx] = g[0][kx];
        t4[1][kx] = 0.5f*(g[0][kx] + g[1][kx] + g[2][kx]);
        t4[2][kx] = 0.5f*(g[0][kx] - g[1][kx] + g[2][kx]);
        t4[3][kx] = g[2][kx];
    }
#pragma unroll
    for (int jy = 0; jy < 4; jy++) {
        float a = t4[jy][0], bq = t4[jy][1], c = t4[jy][2];
        float u0 = a;
        float u1 = 0.5f*(a + bq + c);
        float u2 = 0.5f*(a - bq + c);
        float u3 = c;
        d_U[(((size_t)conv*16 + jy*4 + 0)*64 + ci)*64 + co] = u0;
        d_U[(((size_t)conv*16 + jy*4 + 1)*64 + ci)*64 + co] = u1;
        d_U[(((size_t)conv*16 + jy*4 + 2)*64 + ci)*64 + co] = u2;
        d_U[(((size_t)conv*16 + jy*4 + 3)*64 + ci)*64 + co] = u3;
    }
}

/* ---------------- K4/K5: winograd F(2x2,3x3) conv, C=64 -------------------- */
/* block: 8 n-rows x 32 w = 64 tiles(2x2); 256 threads = tile(64) x coq(4).
   2 blocks/SM (smem 100KB) so Phase A (mem) of one block overlaps Phase B
   (FMA) of the other. U staged in two 8-j halves.
   MODE 1: in = GN(leaky(d_g)) -> out h1 = relu(bn1(conv))
   MODE 2: in = d_h1 -> relu(bn2(conv)+g_act) -> head -> max_k -> out        */
template<int MODE>
__global__ void __launch_bounds__(256, 2) k_wconv(const float* __restrict__ pc,
                                                  float* __restrict__ out) {
    extern __shared__ float smd[];
    float* s_V = smd;                  /* [j16][ci16][TSTR] */
    float* s_U = smd + SV_FLOATS;      /* [j8][ci16][co64]  */
    __shared__ float s_gnsc[64], s_gnsh[64], s_bsc[64], s_bsh[64], s_wc[195];

    int tid = threadIdx.x;
    int b  = blockIdx.x >> 9;
    int n0 = (blockIdx.x & 511) << 3;
    int tile = tid & 63;               /* 0..63 */
    int qtr  = tid >> 6;               /* 0..3 co quarter */
    int tn = tile >> 4, tw = tile & 15;

    if (tid < 64) {
        s_gnsc[tid] = d_par.gnsc[b][tid];
        s_gnsh[tid] = d_par.gnsh[b][tid];
        if (MODE == 1) { s_bsc[tid] = d_par.bn1sc[tid]; s_bsh[tid] = d_par.bn1sh[tid]; }
        else           { s_bsc[tid] = d_par.bn2sc[tid]; s_bsh[tid] = d_par.bn2sh[tid]; }
    }
    if (MODE == 2 && tid < 195) s_wc[tid] = ((const float*)d_par.wc)[tid];

    const float* gin = (MODE == 1 ? d_g : d_h1) + (size_t)b * NPTS * 32 * 64;
    const float* ub  = d_U + (size_t)(MODE - 1) * 65536;

    float racc[64];
#pragma unroll
    for (int q = 0; q < 64; q++) racc[q] = 0.f;

    for (int cc = 0; cc < 64; cc += 16) {
        /* load U half 0 (j = 0..7) */
        for (int u = tid; u < SU_FLOATS; u += 256) {
            int j  = u >> 10;
            int ci = (u >> 6) & 15;
            int co = u & 63;
            s_U[u] = ub[((size_t)j*64 + cc + ci)*64 + co];
        }
        /* Phase A: input transform V = B^T d B (1024 tasks over 256 thr) */
#pragma unroll
        for (int it = 0; it < 4; it++) {
            int uu = it * 256 + tid;
            int tl = uu >> 4, ci = uu & 15;
            int ttn = tl >> 4, ttw = tl & 15;
            int nb = n0 + ttn*2 - 1, wb = ttw*2 - 1;
            int c = cc + ci;
            float gsc = s_gnsc[c], gsh = s_gnsh[c];
            float d[4][4];
#pragma unroll
            for (int y = 0; y < 4; y++) {
                int n = nb + y;
                bool nok = ((unsigned)n < 4096u);
#pragma unroll
                for (int x = 0; x < 4; x++) {
                    int w = wb + x;
                    float v = 0.f;
                    if (nok && (unsigned)w < 32u) {
                        v = gin[((size_t)(n*32 + w))*64 + c];
                        if (MODE == 1) {
                            float tt = fmaf(v, gsc, gsh);
                            v = tt >= 0.f ? tt : 0.2f*tt;
                        }
                    }
                    d[y][x] = v;
                }
            }
            float tA[4][4];
#pragma unroll
            for (int x = 0; x < 4; x++) {
                tA[0][x] = d[0][x] - d[2][x];
                tA[1][x] = d[1][x] + d[2][x];
                tA[2][x] = d[2][x] - d[1][x];
                tA[3][x] = d[1][x] - d[3][x];
            }
#pragma unroll
            for (int jy = 0; jy < 4; jy++) {
                float V0 = tA[jy][0] - tA[jy][2];
                float V1 = tA[jy][1] + tA[jy][2];
                float V2 = tA[jy][2] - tA[jy][1];
                float V3 = tA[jy][1] - tA[jy][3];
                s_V[((jy*4 + 0)*16 + ci)*TSTR + tl] = V0;
                s_V[((jy*4 + 1)*16 + ci)*TSTR + tl] = V1;
                s_V[((jy*4 + 2)*16 + ci)*TSTR + tl] = V2;
                s_V[((jy*4 + 3)*16 + ci)*TSTR + tl] = V3;
            }
        }
        __syncthreads();

        /* Phase B over two U halves */
#pragma unroll 1
        for (int jh = 0; jh < 2; jh++) {
            if (jh == 1) {
                __syncthreads();
                for (int u = tid; u < SU_FLOATS; u += 256) {
                    int j  = u >> 10;
                    int ci = (u >> 6) & 15;
                    int co = u & 63;
                    s_U[u] = ub[((size_t)(8 + j)*64 + cc + ci)*64 + co];
                }
                __syncthreads();
            }
#pragma unroll 1
            for (int jl = 0; jl < 8; jl++) {
                int j = jh*8 + jl;
                float m[16];
#pragma unroll
                for (int k = 0; k < 16; k++) m[k] = 0.f;
                const float* vp = s_V + (j*16)*TSTR + tile;
                const float* up = s_U + (jl*16)*64 + qtr*16;
#pragma unroll
                for (int ci = 0; ci < 16; ci++) {
                    float v = vp[ci*TSTR];
                    const float4* ur = (const float4*)(up + ci*64);
                    float4 u0 = ur[0], u1 = ur[1], u2 = ur[2], u3 = ur[3];
                    m[0]  = fmaf(v, u0.x, m[0]);  m[1]  = fmaf(v, u0.y, m[1]);
                    m[2]  = fmaf(v, u0.z, m[2]);  m[3]  = fmaf(v, u0.w, m[3]);
                    m[4]  = fmaf(v, u1.x, m[4]);  m[5]  = fmaf(v, u1.y, m[5]);
                    m[6]  = fmaf(v, u1.z, m[6]);  m[7]  = fmaf(v, u1.w, m[7]);
                    m[8]  = fmaf(v, u2.x, m[8]);  m[9]  = fmaf(v, u2.y, m[9]);
                    m[10] = fmaf(v, u2.z, m[10]); m[11] = fmaf(v, u2.w, m[11]);
                    m[12] = fmaf(v, u3.x, m[12]); m[13] = fmaf(v, u3.y, m[13]);
                    m[14] = fmaf(v, u3.z, m[14]); m[15] = fmaf(v, u3.w, m[15]);
                }
                int jy = j >> 2, jx = j & 3;
                float cy[2], cx[2];
                cy[0] = (jy == 3) ? 0.f : 1.f;
                cy[1] = (jy == 0) ? 0.f : ((jy == 1) ? 1.f : -1.f);
                cx[0] = (jx == 3) ? 0.f : 1.f;
                cx[1] = (jx == 0) ? 0.f : ((jx == 1) ? 1.f : -1.f);
#pragma unroll
                for (int py = 0; py < 2; py++) {
#pragma unroll
                    for (int px = 0; px < 2; px++) {
                        float cf = cy[py] * cx[px];
                        if (cf != 0.f) {
                            float* o = racc + (py*2 + px)*16;
#pragma unroll
                            for (int k = 0; k < 16; k++) o[k] = fmaf(cf, m[k], o[k]);
                        }
                    }
                }
            }
        }
        __syncthreads();
    }

    /* ------------------------------ epilogue ------------------------------- */
    if (MODE == 1) {
#pragma unroll
        for (int py = 0; py < 2; py++) {
#pragma unroll
            for (int px = 0; px < 2; px++) {
                int n = n0 + tn*2 + py, w = tw*2 + px;
                size_t pix = ((size_t)(b*NPTS + n))*32 + w;
                float* op = d_h1 + pix*64 + qtr*16;
                const float* a = racc + (py*2 + px)*16;
#pragma unroll
                for (int q = 0; q < 4; q++) {
                    int c = qtr*16 + q*4;
                    float4 v;
                    v.x = fmaxf(fmaf(a[q*4+0], s_bsc[c+0], s_bsh[c+0]), 0.f);
                    v.y = fmaxf(fmaf(a[q*4+1], s_bsc[c+1], s_bsh[c+1]), 0.f);
                    v.z = fmaxf(fmaf(a[q*4+2], s_bsc[c+2], s_bsh[c+2]), 0.f);
                    v.w = fmaxf(fmaf(a[q*4+3], s_bsc[c+3], s_bsh[c+3]), 0.f);
                    *(float4*)(op + q*4) = v;
                }
            }
        }
    } else {
        float* yp = s_V;   /* alias: [8n][32w][4q][3] = 3072 floats */
#pragma unroll
        for (int py = 0; py < 2; py++) {
#pragma unroll
            for (int px = 0; px < 2; px++) {
                int nl = tn*2 + py, w = tw*2 + px;
                size_t pix = ((size_t)(b*NPTS + n0 + nl))*32 + w;
                const float* a = racc + (py*2 + px)*16;
                float4 g4[4];
#pragma unroll
                for (int q = 0; q < 4; q++)
                    g4[q] = ((const float4*)(d_g + pix*64 + qtr*16))[q];
                const float* gf = (const float*)g4;
                float y0 = 0.f, y1 = 0.f, y2 = 0.f;
#pragma unroll
                for (int k = 0; k < 16; k++) {
                    int c = qtr*16 + k;
                    float gv = fmaf(gf[k], s_gnsc[c], s_gnsh[c]);
                    gv = gv >= 0.f ? gv : 0.2f*gv;
                    float h = fmaxf(fmaf(a[k], s_bsc[c], s_bsh[c]) + gv, 0.f);
                    y0 = fmaf(h, s_wc[c], y0);
                    y1 = fmaf(h, s_wc[64+c], y1);
                    y2 = fmaf(h, s_wc[128+c], y2);
                }
                int idx = ((nl*32 + w)*4 + qtr)*3;
                yp[idx] = y0; yp[idx+1] = y1; yp[idx+2] = y2;
            }
        }
        __syncthreads();
        {
            int nl = tid >> 5, w = tid & 31;
            float y0 = s_wc[192], y1 = s_wc[193], y2 = s_wc[194];
#pragma unroll
            for (int q = 0; q < 4; q++) {
                int idx = ((nl*32 + w)*4 + q)*3;
                y0 += yp[idx]; y1 += yp[idx+1]; y2 += yp[idx+2];
            }
#pragma unroll
            for (int off = 16; off; off >>= 1) {
                y0 = fmaxf(y0, __shfl_xor_sync(0xffffffffu, y0, off));
                y1 = fmaxf(y1, __shfl_xor_sync(0xffffffffu, y1, off));
                y2 = fmaxf(y2, __shfl_xor_sync(0xffffffffu, y2, off));
            }
            if (w == 0) {
                int n = n0 + nl;
                const float* pp = pc + ((size_t)(b*NPTS + n)) * 3;
                float* o = out + ((size_t)(b*NPTS + n)) * 6;
                o[0] = pp[0]; o[1] = pp[1]; o[2] = pp[2];
                float c0 = 1.f / (1.f + expf(-y0));
                float c1 = 1.f / (1.f + expf(-y1));
                float c2 = 1.f / (1.f + expf(-y2));
                o[3] = (c0 - 0.485f) / 0.229f;
                o[4] = (c1 - 0.456f) / 0.224f;
                o[5] = (c2 - 0.406f) / 0.225f;
            }
        }
    }
}

/* --------------------------------- launcher -------------------------------- */
extern "C" void kernel_launch(void* const* d_in, const int* in_sizes, int n_in,
                              void* d_out, int out_size) {
    const float* opc   = (const float*)d_in[0];
    const float* pc    = (const float*)d_in[1];
    const float* w_in  = (const float*)d_in[2];
    const float* b_in  = (const float*)d_in[3];
    const float* w_g   = (const float*)d_in[4];
    const float* gn_g  = (const float*)d_in[5];
    const float* gn_b  = (const float*)d_in[6];
    const float* w_c1  = (const float*)d_in[7];
    const float* bn1_g = (const float*)d_in[8];
    const float* bn1_b = (const float*)d_in[9];
    const float* bn1_m = (const float*)d_in[10];
    const float* bn1_v = (const float*)d_in[11];
    const float* w_c2  = (const float*)d_in[12];
    const float* bn2_g = (const float*)d_in[13];
    const float* bn2_b = (const float*)d_in[14];
    const float* bn2_m = (const float*)d_in[15];
    const float* bn2_v = (const float*)d_in[16];
    const float* w_blk = (const float*)d_in[17];
    const float* b_blk = (const float*)d_in[18];
    const float* w_img = (const float*)d_in[19];
    const float* b_img = (const float*)d_in[20];
    float* out = (float*)d_out;

    cudaFuncSetAttribute(k_knn, cudaFuncAttributeMaxDynamicSharedMemorySize, 65536);
    cudaFuncSetAttribute(k_wconv<1>, cudaFuncAttributeMaxDynamicSharedMemorySize, WCONV_SMEM);
    cudaFuncSetAttribute(k_wconv<2>, cudaFuncAttributeMaxDynamicSharedMemorySize, WCONV_SMEM);

    k_f    <<<64,   256>>>(opc, w_in, b_in);
    k_knn  <<<2048, 256, 65536>>>(opc);
    k_edge <<<2048, 256>>>(w_g);
    k_final<<<1,    256>>>(gn_g, gn_b, bn1_g, bn1_b, bn1_m, bn1_v,
                           bn2_g, bn2_b, bn2_m, bn2_v, w_blk, b_blk, w_img, b_img);
    k_uprep<<<32,   256>>>(w_c1, w_c2);
    k_wconv<1><<<2048, 256, WCONV_SMEM>>>(pc, out);
    k_wconv<2><<<2048, 256, WCONV_SMEM>>>(pc, out);
}

// round 16
// speedup vs baseline: 1.5948x; 1.4730x over previous
#include <cuda_runtime.h>
#include <cuda_bf16.h>
#include <math.h>
#include <stdint.h>

#define NBATCH 4
#define NPTS   4096
#define KNB    32
#define NPIXT  (NBATCH*NPTS*KNB)   /* 524288 pixels */

/* winograd conv smem: V[16j][16ci][66] + U[8j][16ci][64co] floats */
#define TSTR   66
#define SV_FLOATS (16*16*TSTR)         /* 16896 */
#define SU_FLOATS (8*16*64)            /* 8192  */
#define WCONV_SMEM ((SV_FLOATS + SU_FLOATS)*4)   /* 100352 B -> 2 blocks/SM */

/* ----------------------------- device scratch ----------------------------- */
__device__ float d_f[NBATCH*NPTS*8];
__device__ int   d_idx[NPIXT];
__device__ float d_g [(size_t)NPIXT*64];   /* raw graph feats (pre-GN) */
__device__ float d_h1[(size_t)NPIXT*64];   /* conv1 activated output   */
__device__ float d_stats[32];              /* [b][grp][sum,sumsq]      */
__device__ float d_U[2*16*64*64];          /* winograd weights [conv][j][ci][co] */

struct Params {
    float gnsc[4][64];
    float gnsh[4][64];
    float bn1sc[64], bn1sh[64];
    float bn2sc[64], bn2sh[64];
    float wc[3][64];               /* folded w_img @ w_blk */
    float bc[3];                   /* folded bias          */
};
__device__ Params d_par;

/* ------------------------- K0: input MLP f = opc@W+b ----------------------- */
__global__ void k_f(const float* __restrict__ opc, const float* __restrict__ w_in,
                    const float* __restrict__ b_in) {
    int t = blockIdx.x * 256 + threadIdx.x;            /* 0..16383 */
    if (blockIdx.x == 0 && threadIdx.x < 32) d_stats[threadIdx.x] = 0.f;
    const float* p = opc + (size_t)t * 3;
    float x = p[0], y = p[1], z = p[2];
#pragma unroll
    for (int d = 0; d < 8; d++) {
        float a = __ldg(b_in + d);
        a = fmaf(x, __ldg(w_in + d*3 + 0), a);
        a = fmaf(y, __ldg(w_in + d*3 + 1), a);
        a = fmaf(z, __ldg(w_in + d*3 + 2), a);
        d_f[(size_t)t*8 + d] = a;
    }
}

/* ------------------------------ K1: exact KNN ------------------------------ */
/* warp-distributed sorted top-32: lane k holds k-th smallest u64 key
   (sortbits(dist)<<32 | idx). Batch ballot against current 32nd-best;
   only qualifying candidates inserted (cheap warp shift each).           */
__global__ void __launch_bounds__(256) k_knn(const float* __restrict__ opc) {
    extern __shared__ float sm[];
    float* px  = sm;
    float* py  = sm + 4096;
    float* pz  = sm + 8192;
    float* psq = sm + 12288;
    int tid = threadIdx.x;
    int b = blockIdx.x >> 9;
    const float* base = opc + (size_t)b * NPTS * 3;
    for (int i = tid; i < NPTS; i += 256) {
        float x = base[i*3], y = base[i*3+1], z = base[i*3+2];
        px[i] = x; py[i] = y; pz[i] = z;
        psq[i] = __fadd_rn(__fadd_rn(__fmul_rn(x,x), __fmul_rn(y,y)), __fmul_rn(z,z));
    }
    __syncthreads();

    int warp = tid >> 5, lane = tid & 31;
    int nq = (blockIdx.x & 511) * 8 + warp;
    float qx = px[nq], qy = py[nq], qz = pz[nq], qs = psq[nq];

    unsigned long long cur  = ~0ull;    /* lane k: k-th smallest so far */
    unsigned long long kmax = ~0ull;    /* = cur at lane 31 (warp-uniform) */

    for (int m0 = 0; m0 < NPTS; m0 += 32) {
        int m = m0 + lane;
        float dot  = __fadd_rn(__fadd_rn(__fmul_rn(qx, px[m]), __fmul_rn(qy, py[m])),
                               __fmul_rn(qz, pz[m]));
        float dist = __fsub_rn(__fadd_rn(qs, psq[m]), __fmul_rn(2.0f, dot));
        unsigned u = __float_as_uint(dist);
        u = (u & 0x80000000u) ? ~u : (u | 0x80000000u);
        unsigned long long key = ((unsigned long long)u << 32) | (unsigned)m;

        unsigned qmask = __ballot_sync(0xffffffffu, key < kmax);
        while (qmask) {
            int src = __ffs(qmask) - 1;
            qmask &= qmask - 1;
            unsigned long long k2 = __shfl_sync(0xffffffffu, key, src);
            /* insert k2 into the distributed sorted list */
            unsigned gt = __ballot_sync(0xffffffffu, cur > k2);   /* contiguous high mask, nonzero */
            unsigned long long prev = __shfl_up_sync(0xffffffffu, cur, 1);
            int pos = __ffs(gt) - 1;
            if (lane >= pos) cur = (lane == pos) ? k2 : prev;
            kmax = __shfl_sync(0xffffffffu, cur, 31);
            qmask &= __ballot_sync(0xffffffffu, key < kmax);
        }
    }
    d_idx[((size_t)(b * NPTS + nq)) * 32 + lane] = (int)(cur & 0xffffffffu);
}

/* ----------------- K2: edge features + 16->64 GEMM + GN stats -------------- */
__global__ void __launch_bounds__(256) k_edge(const float* __restrict__ wg) {
    __shared__ float swg[1024];
    __shared__ float ssum[8];
    int tid = threadIdx.x;
    for (int u = tid; u < 1024; u += 256) swg[u] = wg[u];
    if (tid < 8) ssum[tid] = 0.f;
    __syncthreads();

    int p = blockIdx.x * 256 + tid;
    int b = p >> 17;
    int n = (p >> 5) & 4095;
    int id = d_idx[p];
    const float4* fq4 = (const float4*)(d_f + (size_t)(b*NPTS + n ) * 8);
    const float4* nb4 = (const float4*)(d_f + (size_t)(b*NPTS + id) * 8);
    float4 fa = fq4[0], fb = fq4[1], na = nb4[0], nb = nb4[1];

    float feat[16];
    feat[0] = na.x - fa.x; feat[1] = na.y - fa.y; feat[2] = na.z - fa.z; feat[3] = na.w - fa.w;
    feat[4] = nb.x - fb.x; feat[5] = nb.y - fb.y; feat[6] = nb.z - fb.z; feat[7] = nb.w - fb.w;
    feat[8]  = fa.x; feat[9]  = fa.y; feat[10] = fa.z; feat[11] = fa.w;
    feat[12] = fb.x; feat[13] = fb.y; feat[14] = fb.z; feat[15] = fb.w;

    float* gout = d_g + (size_t)p * 64;
    float ps[4], pss[4];
#pragma unroll
    for (int g = 0; g < 4; g++) { ps[g] = 0.f; pss[g] = 0.f; }

#pragma unroll
    for (int d0 = 0; d0 < 64; d0 += 4) {
        float4 o;
        float* opp = (float*)&o;
#pragma unroll
        for (int s = 0; s < 4; s++) {
            int d = d0 + s;
            const float4* wr = (const float4*)(swg + d * 16);
            float a = 0.f;
#pragma unroll
            for (int t = 0; t < 4; t++) {
                float4 wv = wr[t];
                a = fmaf(feat[4*t+0], wv.x, a);
                a = fmaf(feat[4*t+1], wv.y, a);
                a = fmaf(feat[4*t+2], wv.z, a);
                a = fmaf(feat[4*t+3], wv.w, a);
            }
            opp[s] = a;
            ps[d0 >> 4] += a;
            pss[d0 >> 4] = fmaf(a, a, pss[d0 >> 4]);
        }
        *(float4*)(gout + d0) = o;
    }

#pragma unroll
    for (int g = 0; g < 4; g++) {
#pragma unroll
        for (int off = 16; off; off >>= 1) {
            ps[g]  += __shfl_xor_sync(0xffffffffu, ps[g],  off);
            pss[g] += __shfl_xor_sync(0xffffffffu, pss[g], off);
        }
    }
    if ((tid & 31) == 0) {
#pragma unroll
        for (int g = 0; g < 4; g++) {
            atomicAdd(&ssum[2*g],   ps[g]);
            atomicAdd(&ssum[2*g+1], pss[g]);
        }
    }
    __syncthreads();
    if (tid < 8) atomicAdd(&d_stats[b*8 + tid], ssum[tid]);
}

/* -------------------- K3: finalize all derived parameters ------------------ */
__global__ void k_final(const float* __restrict__ gn_g, const float* __restrict__ gn_b,
                        const float* __restrict__ bn1_g, const float* __restrict__ bn1_b,
                        const float* __restrict__ bn1_m, const float* __restrict__ bn1_v,
                        const float* __restrict__ bn2_g, const float* __restrict__ bn2_b,
                        const float* __restrict__ bn2_m, const float* __restrict__ bn2_v,
                        const float* __restrict__ w_blk, const float* __restrict__ b_blk,
                        const float* __restrict__ w_img, const float* __restrict__ b_img) {
    __shared__ float smu[16], srs[16];
    int tid = threadIdx.x;
    const float inv = 1.0f / 2097152.0f;   /* N*K*16 */
    if (tid < 16) {
        float s  = d_stats[ (tid>>2)*8 + (tid&3)*2 ];
        float ss = d_stats[ (tid>>2)*8 + (tid&3)*2 + 1 ];
        float mu = s * inv;
        float var = ss * inv - mu * mu;
        smu[tid] = mu;
        srs[tid] = rsqrtf(var + 1e-5f);
    }
    __syncthreads();
    {   /* GN affine per (b,d): 256 entries */
        int b = tid >> 6, d = tid & 63, grp = d >> 4;
        float rs = srs[b*4 + grp], mu = smu[b*4 + grp];
        float sc = gn_g[d] * rs;
        d_par.gnsc[b][d] = sc;
        d_par.gnsh[b][d] = gn_b[d] - mu * sc;
    }
    if (tid < 64) {
        int d = tid;
        float s1 = bn1_g[d] * rsqrtf(bn1_v[d] + 1e-5f);
        d_par.bn1sc[d] = s1; d_par.bn1sh[d] = bn1_b[d] - bn1_m[d] * s1;
        float s2 = bn2_g[d] * rsqrtf(bn2_v[d] + 1e-5f);
        d_par.bn2sc[d] = s2; d_par.bn2sh[d] = bn2_b[d] - bn2_m[d] * s2;
    }
    if (tid < 192) {
        int i = tid >> 6, c = tid & 63;
        float a = 0.f;
        for (int d = 0; d < 64; d++) a = fmaf(w_img[i*64 + d], w_blk[d*64 + c], a);
        d_par.wc[i][c] = a;
    }
    if (tid < 3) {
        float a = b_img[tid];
        for (int d = 0; d < 64; d++) a = fmaf(w_img[tid*64 + d], b_blk[d], a);
        d_par.bc[tid] = a;
    }
}

/* --------------- K_uprep: winograd weight transform U = G g G^T ------------ */
__global__ void k_uprep(const float* __restrict__ w1, const float* __restrict__ w2) {
    int t = blockIdx.x * 256 + threadIdx.x;       /* 0..8191 */
    if (t >= 8192) return;
    int conv = t >> 12;
    int r = t & 4095;
    int ci = r >> 6, co = r & 63;
    const float* w = conv ? w2 : w1;
    float g[3][3];
#pragma unroll
    for (int ky = 0; ky < 3; ky++)
#pragma unroll
        for (int kx = 0; kx < 3; kx++)
            g[ky][kx] = w[(((size_t)ky*3 + kx)*64 + ci)*64 + co];
    float t4[4][3];
#pragma unroll
    for (int kx = 0; kx < 3; kx++) {
        t4[0][kx] = g[0][kx];
        t4[1][kx] = 0.5f*(g[0][kx] + g[1][kx] + g[2][kx]);
        t4[2][kx] = 0.5f*(g[0][kx] - g[1][kx] + g[2][kx]);
        t4[3][kx] = g[2][kx];
    }
#pragma unroll
    for (int jy = 0; jy < 4; jy++) {
        float a = t4[jy][0], bq = t4[jy][1], c = t4[jy][2];
        float u0 = a;
        float u1 = 0.5f*(a + bq + c);
        float u2 = 0.5f*(a - bq + c);
        float u3 = c;
        d_U[(((size_t)conv*16 + jy*4 + 0)*64 + ci)*64 + co] = u0;
        d_U[(((size_t)conv*16 + jy*4 + 1)*64 + ci)*64 + co] = u1;
        d_U[(((size_t)conv*16 + jy*4 + 2)*64 + ci)*64 + co] = u2;
        d_U[(((size_t)conv*16 + jy*4 + 3)*64 + ci)*64 + co] = u3;
    }
}

/* ---------------- K4/K5: winograd F(2x2,3x3) conv, C=64 -------------------- */
/* block: 8 n-rows x 32 w = 64 tiles(2x2); 256 threads = tile(64) x coq(4).
   2 blocks/SM (smem 100KB). U staged in two 8-j halves.
   MODE 1: in = GN(leaky(d_g)) -> out h1 = relu(bn1(conv))
   MODE 2: in = d_h1 -> relu(bn2(conv)+g_act) -> head -> max_k -> out        */
template<int MODE>
__global__ void __launch_bounds__(256, 2) k_wconv(const float* __restrict__ pc,
                                                  float* __restrict__ out) {
    extern __shared__ float smd[];
    float* s_V = smd;                  /* [j16][ci16][TSTR] */
    float* s_U = smd + SV_FLOATS;      /* [j8][ci16][co64]  */
    __shared__ float s_gnsc[64], s_gnsh[64], s_bsc[64], s_bsh[64], s_wc[195];

    int tid = threadIdx.x;
    int b  = blockIdx.x >> 9;
    int n0 = (blockIdx.x & 511) << 3;
    int tile = tid & 63;               /* 0..63 */
    int qtr  = tid >> 6;               /* 0..3 co quarter */
    int tn = tile >> 4, tw = tile & 15;

    if (tid < 64) {
        s_gnsc[tid] = d_par.gnsc[b][tid];
        s_gnsh[tid] = d_par.gnsh[b][tid];
        if (MODE == 1) { s_bsc[tid] = d_par.bn1sc[tid]; s_bsh[tid] = d_par.bn1sh[tid]; }
        else           { s_bsc[tid] = d_par.bn2sc[tid]; s_bsh[tid] = d_par.bn2sh[tid]; }
    }
    if (MODE == 2 && tid < 195) s_wc[tid] = ((const float*)d_par.wc)[tid];

    const float* gin = (MODE == 1 ? d_g : d_h1) + (size_t)b * NPTS * 32 * 64;
    const float* ub  = d_U + (size_t)(MODE - 1) * 65536;

    float racc[64];
#pragma unroll
    for (int q = 0; q < 64; q++) racc[q] = 0.f;

    for (int cc = 0; cc < 64; cc += 16) {
        /* load U half 0 (j = 0..7) */
        for (int u = tid; u < SU_FLOATS; u += 256) {
            int j  = u >> 10;
            int ci = (u >> 6) & 15;
            int co = u & 63;
            s_U[u] = ub[((size_t)j*64 + cc + ci)*64 + co];
        }
        /* Phase A: input transform V = B^T d B (1024 tasks over 256 thr) */
#pragma unroll
        for (int it = 0; it < 4; it++) {
            int uu = it * 256 + tid;
            int tl = uu >> 4, ci = uu & 15;
            int ttn = tl >> 4, ttw = tl & 15;
            int nb = n0 + ttn*2 - 1, wb = ttw*2 - 1;
            int c = cc + ci;
            float gsc = s_gnsc[c], gsh = s_gnsh[c];
            float d[4][4];
#pragma unroll
            for (int y = 0; y < 4; y++) {
                int n = nb + y;
                bool nok = ((unsigned)n < 4096u);
#pragma unroll
                for (int x = 0; x < 4; x++) {
                    int w = wb + x;
                    float v = 0.f;
                    if (nok && (unsigned)w < 32u) {
                        v = gin[((size_t)(n*32 + w))*64 + c];
                        if (MODE == 1) {
                            float tt = fmaf(v, gsc, gsh);
                            v = tt >= 0.f ? tt : 0.2f*tt;
                        }
                    }
                    d[y][x] = v;
                }
            }
            float tA[4][4];
#pragma unroll
            for (int x = 0; x < 4; x++) {
                tA[0][x] = d[0][x] - d[2][x];
                tA[1][x] = d[1][x] + d[2][x];
                tA[2][x] = d[2][x] - d[1][x];
                tA[3][x] = d[1][x] - d[3][x];
            }
#pragma unroll
            for (int jy = 0; jy < 4; jy++) {
                float V0 = tA[jy][0] - tA[jy][2];
                float V1 = tA[jy][1] + tA[jy][2];
                float V2 = tA[jy][2] - tA[jy][1];
                float V3 = tA[jy][1] - tA[jy][3];
                s_V[((jy*4 + 0)*16 + ci)*TSTR + tl] = V0;
                s_V[((jy*4 + 1)*16 + ci)*TSTR + tl] = V1;
                s_V[((jy*4 + 2)*16 + ci)*TSTR + tl] = V2;
                s_V[((jy*4 + 3)*16 + ci)*TSTR + tl] = V3;
            }
        }
        __syncthreads();

        /* Phase B over two U halves */
#pragma unroll 1
        for (int jh = 0; jh < 2; jh++) {
            if (jh == 1) {
                __syncthreads();
                for (int u = tid; u < SU_FLOATS; u += 256) {
                    int j  = u >> 10;
                    int ci = (u >> 6) & 15;
                    int co = u & 63;
                    s_U[u] = ub[((size_t)(8 + j)*64 + cc + ci)*64 + co];
                }
                __syncthreads();
            }
#pragma unroll 1
            for (int jl = 0; jl < 8; jl++) {
                int j = jh*8 + jl;
                float m[16];
#pragma unroll
                for (int k = 0; k < 16; k++) m[k] = 0.f;
                const float* vp = s_V + (j*16)*TSTR + tile;
                const float* up = s_U + (jl*16)*64 + qtr*16;
#pragma unroll
                for (int ci = 0; ci < 16; ci++) {
                    float v = vp[ci*TSTR];
                    const float4* ur = (const float4*)(up + ci*64);
                    float4 u0 = ur[0], u1 = ur[1], u2 = ur[2], u3 = ur[3];
                    m[0]  = fmaf(v, u0.x, m[0]);  m[1]  = fmaf(v, u0.y, m[1]);
                    m[2]  = fmaf(v, u0.z, m[2]);  m[3]  = fmaf(v, u0.w, m[3]);
                    m[4]  = fmaf(v, u1.x, m[4]);  m[5]  = fmaf(v, u1.y, m[5]);
                    m[6]  = fmaf(v, u1.z, m[6]);  m[7]  = fmaf(v, u1.w, m[7]);
                    m[8]  = fmaf(v, u2.x, m[8]);  m[9]  = fmaf(v, u2.y, m[9]);
                    m[10] = fmaf(v, u2.z, m[10]); m[11] = fmaf(v, u2.w, m[11]);
                    m[12] = fmaf(v, u3.x, m[12]); m[13] = fmaf(v, u3.y, m[13]);
                    m[14] = fmaf(v, u3.z, m[14]); m[15] = fmaf(v, u3.w, m[15]);
                }
                int jy = j >> 2, jx = j & 3;
                float cy[2], cx[2];
                cy[0] = (jy == 3) ? 0.f : 1.f;
                cy[1] = (jy == 0) ? 0.f : ((jy == 1) ? 1.f : -1.f);
                cx[0] = (jx == 3) ? 0.f : 1.f;
                cx[1] = (jx == 0) ? 0.f : ((jx == 1) ? 1.f : -1.f);
#pragma unroll
                for (int py = 0; py < 2; py++) {
#pragma unroll
                    for (int px = 0; px < 2; px++) {
                        float cf = cy[py] * cx[px];
                        if (cf != 0.f) {
                            float* o = racc + (py*2 + px)*16;
#pragma unroll
                            for (int k = 0; k < 16; k++) o[k] = fmaf(cf, m[k], o[k]);
                        }
                    }
                }
            }
        }
        __syncthreads();
    }

    /* ------------------------------ epilogue ------------------------------- */
    if (MODE == 1) {
#pragma unroll
        for (int py = 0; py < 2; py++) {
#pragma unroll
            for (int px = 0; px < 2; px++) {
                int n = n0 + tn*2 + py, w = tw*2 + px;
                size_t pix = ((size_t)(b*NPTS + n))*32 + w;
                float* op = d_h1 + pix*64 + qtr*16;
                const float* a = racc + (py*2 + px)*16;
#pragma unroll
                for (int q = 0; q < 4; q++) {
                    int c = qtr*16 + q*4;
                    float4 v;
                    v.x = fmaxf(fmaf(a[q*4+0], s_bsc[c+0], s_bsh[c+0]), 0.f);
                    v.y = fmaxf(fmaf(a[q*4+1], s_bsc[c+1], s_bsh[c+1]), 0.f);
                    v.z = fmaxf(fmaf(a[q*4+2], s_bsc[c+2], s_bsh[c+2]), 0.f);
                    v.w = fmaxf(fmaf(a[q*4+3], s_bsc[c+3], s_bsh[c+3]), 0.f);
                    *(float4*)(op + q*4) = v;
                }
            }
        }
    } else {
        float* yp = s_V;   /* alias: [8n][32w][4q][3] = 3072 floats */
#pragma unroll
        for (int py = 0; py < 2; py++) {
#pragma unroll
            for (int px = 0; px < 2; px++) {
                int nl = tn*2 + py, w = tw*2 + px;
                size_t pix = ((size_t)(b*NPTS + n0 + nl))*32 + w;
                const float* a = racc + (py*2 + px)*16;
                float4 g4[4];
#pragma unroll
                for (int q = 0; q < 4; q++)
                    g4[q] = ((const float4*)(d_g + pix*64 + qtr*16))[q];
                const float* gf = (const float*)g4;
                float y0 = 0.f, y1 = 0.f, y2 = 0.f;
#pragma unroll
                for (int k = 0; k < 16; k++) {
                    int c = qtr*16 + k;
                    float gv = fmaf(gf[k], s_gnsc[c], s_gnsh[c]);
                    gv = gv >= 0.f ? gv : 0.2f*gv;
                    float h = fmaxf(fmaf(a[k], s_bsc[c], s_bsh[c]) + gv, 0.f);
                    y0 = fmaf(h, s_wc[c], y0);
                    y1 = fmaf(h, s_wc[64+c], y1);
                    y2 = fmaf(h, s_wc[128+c], y2);
                }
                int idx = ((nl*32 + w)*4 + qtr)*3;
                yp[idx] = y0; yp[idx+1] = y1; yp[idx+2] = y2;
            }
        }
        __syncthreads();
        {
            int nl = tid >> 5, w = tid & 31;
            float y0 = s_wc[192], y1 = s_wc[193], y2 = s_wc[194];
#pragma unroll
            for (int q = 0; q < 4; q++) {
                int idx = ((nl*32 + w)*4 + q)*3;
                y0 += yp[idx]; y1 += yp[idx+1]; y2 += yp[idx+2];
            }
#pragma unroll
            for (int off = 16; off; off >>= 1) {
                y0 = fmaxf(y0, __shfl_xor_sync(0xffffffffu, y0, off));
                y1 = fmaxf(y1, __shfl_xor_sync(0xffffffffu, y1, off));
                y2 = fmaxf(y2, __shfl_xor_sync(0xffffffffu, y2, off));
            }
            if (w == 0) {
                int n = n0 + nl;
                const float* pp = pc + ((size_t)(b*NPTS + n)) * 3;
                float* o = out + ((size_t)(b*NPTS + n)) * 6;
                o[0] = pp[0]; o[1] = pp[1]; o[2] = pp[2];
                float c0 = 1.f / (1.f + expf(-y0));
                float c1 = 1.f / (1.f + expf(-y1));
                float c2 = 1.f / (1.f + expf(-y2));
                o[3] = (c0 - 0.485f) / 0.229f;
                o[4] = (c1 - 0.456f) / 0.224f;
                o[5] = (c2 - 0.406f) / 0.225f;
            }
        }
    }
}

/* --------------------------------- launcher -------------------------------- */
extern "C" void kernel_launch(void* const* d_in, const int* in_sizes, int n_in,
                              void* d_out, int out_size) {
    const float* opc   = (const float*)d_in[0];
    const float* pc    = (const float*)d_in[1];
    const float* w_in  = (const float*)d_in[2];
    const float* b_in  = (const float*)d_in[3];
    const float* w_g   = (const float*)d_in[4];
    const float* gn_g  = (const float*)d_in[5];
    const float* gn_b  = (const float*)d_in[6];
    const float* w_c1  = (const float*)d_in[7];
    const float* bn1_g = (const float*)d_in[8];
    const float* bn1_b = (const float*)d_in[9];
    const float* bn1_m = (const float*)d_in[10];
    const float* bn1_v = (const float*)d_in[11];
    const float* w_c2  = (const float*)d_in[12];
    const float* bn2_g = (const float*)d_in[13];
    const float* bn2_b = (const float*)d_in[14];
    const float* bn2_m = (const float*)d_in[15];
    const float* bn2_v = (const float*)d_in[16];
    const float* w_blk = (const float*)d_in[17];
    const float* b_blk = (const float*)d_in[18];
    const float* w_img = (const float*)d_in[19];
    const float* b_img = (const float*)d_in[20];
    float* out = (float*)d_out;

    cudaFuncSetAttribute(k_knn, cudaFuncAttributeMaxDynamicSharedMemorySize, 65536);
    cudaFuncSetAttribute(k_wconv<1>, cudaFuncAttributeMaxDynamicSharedMemorySize, WCONV_SMEM);
    cudaFuncSetAttribute(k_wconv<2>, cudaFuncAttributeMaxDynamicSharedMemorySize, WCONV_SMEM);

    k_f    <<<64,   256>>>(opc, w_in, b_in);
    k_knn  <<<2048, 256, 65536>>>(opc);
    k_edge <<<2048, 256>>>(w_g);
    k_final<<<1,    256>>>(gn_g, gn_b, bn1_g, bn1_b, bn1_m, bn1_v,
                           bn2_g, bn2_b, bn2_m, bn2_v, w_blk, b_blk, w_img, b_img);
    k_uprep<<<32,   256>>>(w_c1, w_c2);
    k_wconv<1><<<2048, 256, WCONV_SMEM>>>(pc, out);
    k_wconv<2><<<2048, 256, WCONV_SMEM>>>(pc, out);
}